// round 1
// baseline (speedup 1.0000x reference)
#include <cuda_runtime.h>

#define NW      10000
#define MAXLEN  14
#define QCOUNT  32     // BSZ*SEQ
#define TPB     128

// Scratch (no allocation allowed): sorted word metadata
__device__ int   g_wlen_s[NW];
__device__ int   g_orig_s[NW];
__device__ uint4 g_packed[NW];

// -------------------------------------------------------------------------
// Pre-kernel: counting-sort words by length; pack 14 chars into 4 uint32.
// Order within a bucket is atomic-nondeterministic, but the main kernel
// scatters by original index, so the final output is deterministic.
// -------------------------------------------------------------------------
__global__ void sort_pack_kernel(const int* __restrict__ words,
                                 const int* __restrict__ wl) {
    __shared__ int hist[MAXLEN + 2];
    __shared__ int offs[MAXLEN + 2];
    int tid = threadIdx.x;
    if (tid <= MAXLEN + 1) hist[tid] = 0;
    __syncthreads();
    for (int w = tid; w < NW; w += blockDim.x)
        atomicAdd(&hist[wl[w]], 1);
    __syncthreads();
    if (tid == 0) {
        int acc = 0;
        for (int l = 1; l <= MAXLEN; ++l) { offs[l] = acc; acc += hist[l]; }
    }
    __syncthreads();
    for (int w = tid; w < NW; w += blockDim.x) {
        int len = wl[w];
        int pos = atomicAdd(&offs[len], 1);
        g_wlen_s[pos] = len;
        g_orig_s[pos] = w;
        unsigned int p[4] = {0u, 0u, 0u, 0u};
        #pragma unroll
        for (int c = 0; c < MAXLEN; ++c) {
            unsigned int ch = (unsigned int)words[w * MAXLEN + c] & 0xFFu;
            p[c >> 2] |= ch << ((c & 3) * 8);
        }
        g_packed[pos] = make_uint4(p[0], p[1], p[2], p[3]);
    }
}

// -------------------------------------------------------------------------
// Main kernel: block = (word chunk, query). One thread per (query, word).
// d matrix lives in smem as int8 [cell][tid]; previous row in registers.
// Truncated DP: i = 1..swl (uniform per block), j = 1..wlen (warp-uniform
// thanks to the length sort).
// -------------------------------------------------------------------------
__global__ void __launch_bounds__(TPB)
dl_kernel(const int* __restrict__ x, float* __restrict__ out) {
    __shared__ unsigned char d_s[256 * TPB];   // 16x16 cells x TPB threads
    __shared__ int s_x[MAXLEN + 1];

    const int tid  = threadIdx.x;
    const int q    = blockIdx.y;
    const int slot = blockIdx.x * TPB + tid;

    if (tid < MAXLEN + 1) s_x[tid] = x[q * (MAXLEN + 1) + tid];
    __syncthreads();

    // swl = first-argmax over the 15 chars (jnp.argmax semantics)
    int swl = 0, best = s_x[0];
    #pragma unroll
    for (int t = 1; t <= MAXLEN; ++t) {
        int v = s_x[t];
        if (v > best) { best = v; swl = t; }
    }

    int wlen = 0, orig = 0;
    unsigned int pw0 = 0, pw1 = 0, pw2 = 0, pw3 = 0;
    if (slot < NW) {
        wlen = g_wlen_s[slot];
        orig = g_orig_s[slot];
        uint4 p = g_packed[slot];
        pw0 = p.x; pw1 = p.y; pw2 = p.z; pw3 = p.w;
    }

    // Unpack word chars into registers (static after unroll)
    int wc[MAXLEN];
    #pragma unroll
    for (int c = 0; c < MAXLEN; ++c) {
        unsigned int r = (c < 4) ? pw0 : (c < 8) ? pw1 : (c < 12) ? pw2 : pw3;
        wc[c] = (int)((r >> ((c & 3) * 8)) & 0xFFu);
    }
    // kreg[j-1] = da[wc[j-1]] maintained incrementally (monotone in i)
    int kreg[MAXLEN];
    #pragma unroll
    for (int c = 0; c < MAXLEN; ++c) kreg[c] = 0;

    const int maxd = swl + wlen;
    unsigned char* bp = d_s + tid;

    // Init smem cells reachable by the transposition gather (k<=swl-1, l<=wlen-1):
    //   d[0][l] = maxd ; d[1][0] = maxd ; d[1][l] = l-1 (l>=1)
    //   d[k][0] = maxd, d[k][1] = k-1   for k = 2..swl-1
    for (int l = 0; l < wlen; ++l) {
        bp[(0 * 16 + l) * TPB] = (unsigned char)maxd;
        bp[(1 * 16 + l) * TPB] = (unsigned char)(l == 0 ? maxd : l - 1);
    }
    for (int k = 2; k < swl; ++k) {
        bp[(k * 16 + 0) * TPB] = (unsigned char)maxd;
        bp[(k * 16 + 1) * TPB] = (unsigned char)(k - 1);
    }

    // prev[j] = d[i][j]; init to row 1: d[1][j] = j-1 (valid for j<=wlen+1)
    int prev[16];
    #pragma unroll
    for (int j = 1; j <= 15; ++j) prev[j] = j - 1;

    int res = wlen;                 // swl == 0 case: d[1][wlen+1] = wlen
    for (int i = 1; i <= swl; ++i) {   // uniform trip count per block
        const int xc = s_x[i - 1];
        int db   = 0;
        int left = i;               // d[i+1][1] = i (i <= swl)
        unsigned char* rowp = bp + ((i + 1) * 16) * TPB;
        #pragma unroll
        for (int j = 1; j <= 15; ++j) {
            if (j > wlen || j == 15) { prev[j] = left; break; }  // epilogue: d[i+1][j]
            const bool p  = (xc == wc[j - 1]);
            const int up   = prev[j + 1];      // d[i][j+1]
            const int diag = prev[j];          // d[i][j]
            const int k = kreg[j - 1];
            const int l = db;
            const int dtr   = (int)bp[(k * 16 + l) * TPB];       // LDS.U8 gather
            const int trans = dtr + (i + j - 1) - k - l;
            int m = min(up + 1, left + 1);
            m = min(m, diag + (p ? 0 : 1));
            m = min(m, trans);
            if (p) { db = j; kreg[j - 1] = i; }  // after use, before next cell
            rowp[(j + 1) * TPB] = (unsigned char)m;  // d[i+1][j+1] for future gathers
            prev[j] = left;                     // becomes row i+1, col j
            left = m;
        }
        res = left;                 // d[i+1][wlen+1]
    }

    if (slot < NW) out[q * NW + orig] = (float)res;
}

// -------------------------------------------------------------------------
extern "C" void kernel_launch(void* const* d_in, const int* in_sizes, int n_in,
                              void* d_out, int out_size) {
    const int* x     = (const int*)d_in[0];   // (2,16,15) int32
    const int* words = (const int*)d_in[1];   // (10000,14) int32
    const int* wl    = (const int*)d_in[2];   // (10000,) int32
    float* out = (float*)d_out;               // (2,16,10000) float32

    sort_pack_kernel<<<1, 1024>>>(words, wl);
    dim3 grid((NW + TPB - 1) / TPB, QCOUNT);
    dl_kernel<<<grid, TPB>>>(x, out);
}

// round 2
// speedup vs baseline: 1.3708x; 1.3708x over previous
#include <cuda_runtime.h>

#define NW      10000
#define MAXLEN  14
#define QCOUNT  32     // BSZ*SEQ
#define TPB     64

// Scratch (no allocation allowed)
__device__ int   g_wlen_s[NW];
__device__ int   g_orig_s[NW];
__device__ uint4 g_packed[NW];
__device__ int   g_offs[MAXLEN + 1];

// -------------------------------------------------------------------------
// Kernel A: histogram of word lengths + exclusive prefix -> g_offs.
// Reads only wl (40 KB) from one block; cheap.
// -------------------------------------------------------------------------
__global__ void hist_kernel(const int* __restrict__ wl) {
    __shared__ int h[MAXLEN + 1];
    int t = threadIdx.x;
    if (t <= MAXLEN) h[t] = 0;
    __syncthreads();
    for (int w = t; w < NW; w += blockDim.x)
        atomicAdd(&h[wl[w]], 1);
    __syncthreads();
    if (t == 0) {
        int acc = 0;
        for (int l = 1; l <= MAXLEN; ++l) { g_offs[l] = acc; acc += h[l]; }
    }
}

// -------------------------------------------------------------------------
// Kernel B: multi-block scatter by length + pack chars to uint4.
// Block-aggregated global atomics (14 per block). Within-bucket order is
// nondeterministic but irrelevant: dl_kernel scatters by original index.
// -------------------------------------------------------------------------
__global__ void scatter_pack_kernel(const int* __restrict__ words,
                                    const int* __restrict__ wl) {
    __shared__ int s_h[MAXLEN + 1];
    __shared__ int s_b[MAXLEN + 1];
    int t = threadIdx.x;
    if (t <= MAXLEN) s_h[t] = 0;
    __syncthreads();
    int w = blockIdx.x * blockDim.x + t;
    int len = 0, rank = 0;
    if (w < NW) { len = wl[w]; rank = atomicAdd(&s_h[len], 1); }
    __syncthreads();
    if (t >= 1 && t <= MAXLEN) s_b[t] = atomicAdd(&g_offs[t], s_h[t]);
    __syncthreads();
    if (w < NW) {
        int pos = s_b[len] + rank;
        g_wlen_s[pos] = len;
        g_orig_s[pos] = w;
        unsigned int p[4] = {0u, 0u, 0u, 0u};
        #pragma unroll
        for (int c = 0; c < MAXLEN; ++c) {
            unsigned int ch = (unsigned int)words[w * MAXLEN + c] & 0xFFu;
            p[c >> 2] |= ch << ((c & 3) * 8);
        }
        g_packed[pos] = make_uint4(p[0], p[1], p[2], p[3]);
    }
}

// -------------------------------------------------------------------------
// Main kernel. One thread per (query, sorted word). Previous DP row in
// registers; a 14x16 per-thread byte matrix in smem serves only the
// transposition gather d[k][l] (k<=swl-1<=13, l<=wlen-1<=13).
// -------------------------------------------------------------------------
__global__ void __launch_bounds__(TPB)
dl_kernel(const int* __restrict__ x, float* __restrict__ out) {
    __shared__ unsigned char d_s[14 * 16 * TPB];   // 224 B per thread
    __shared__ int s_x[MAXLEN + 1];

    const int tid  = threadIdx.x;
    const int q    = blockIdx.y;
    const int slot = blockIdx.x * TPB + tid;

    if (tid < MAXLEN + 1) s_x[tid] = x[q * (MAXLEN + 1) + tid];
    __syncthreads();

    // swl = first-argmax over the 15 chars (jnp.argmax semantics)
    int swl = 0, best = s_x[0];
    #pragma unroll
    for (int t = 1; t <= MAXLEN; ++t) {
        int v = s_x[t];
        if (v > best) { best = v; swl = t; }
    }

    int wlen = 0, orig = 0;
    unsigned int pw0 = 0, pw1 = 0, pw2 = 0, pw3 = 0;
    if (slot < NW) {
        wlen = g_wlen_s[slot];
        orig = g_orig_s[slot];
        uint4 p = g_packed[slot];
        pw0 = p.x; pw1 = p.y; pw2 = p.z; pw3 = p.w;
    }

    int wc[MAXLEN];
    #pragma unroll
    for (int c = 0; c < MAXLEN; ++c) {
        unsigned int r = (c < 4) ? pw0 : (c < 8) ? pw1 : (c < 12) ? pw2 : pw3;
        wc[c] = (int)((r >> ((c & 3) * 8)) & 0xFFu);
    }
    int kreg[MAXLEN];
    #pragma unroll
    for (int c = 0; c < MAXLEN; ++c) kreg[c] = 0;

    const int maxd = swl + wlen;
    unsigned char* bp = d_s + tid;

    // Init gather-reachable boundary cells (rows 0..swl-1, cols 0..wlen-1):
    //   d[0][l] = maxd ; d[1][0] = maxd ; d[1][l>=1] = l-1
    //   d[k][0] = maxd, d[k][1] = k-1   for k = 2..swl-1
    for (int l = 0; l < wlen; ++l) {
        bp[(0 * 16 + l) * TPB] = (unsigned char)maxd;
        bp[(1 * 16 + l) * TPB] = (unsigned char)(l == 0 ? maxd : l - 1);
    }
    for (int k = 2; k < swl; ++k) {
        bp[(k * 16 + 0) * TPB] = (unsigned char)maxd;
        bp[(k * 16 + 1) * TPB] = (unsigned char)(k - 1);
    }

    // prev[j] = d[i][j]; row 1: d[1][j] = j-1
    int prev[16];
    #pragma unroll
    for (int j = 1; j <= 15; ++j) prev[j] = j - 1;

    int res = wlen;                        // swl == 0: d[1][wlen+1] = wlen
    const int rlimit = swl - 2;            // last row index i whose store matters
    const int climit = wlen - 2;           // last col index j whose store matters
    for (int i = 1; i <= swl; ++i) {       // uniform per block
        const int xc  = s_x[i - 1];
        const int im1 = i - 1;
        int db   = 0;
        int left = i;                      // d[i+1][1] = i
        unsigned char* rowp = bp + ((i + 1) * 16) * TPB;
        const bool rkeep = (i <= rlimit);  // store row i+1 only if gatherable
        #pragma unroll
        for (int j = 1; j <= 15; ++j) {
            if (j > wlen || j == 15) { prev[j] = left; break; }   // d[i+1][j]
            const bool p  = (xc == wc[j - 1]);
            const int up   = prev[j + 1];
            const int diag = prev[j];
            const int k = kreg[j - 1];
            const int l = db;
            const int dtr   = (int)bp[(k * 16 + l) * TPB];        // LDS.U8
            const int trans = dtr + (im1 + j - k - l);
            int m = min(up, left) + 1;
            m = min(m, diag + (p ? 0 : 1));
            m = min(m, trans);
            if (p) { db = j; kreg[j - 1] = i; }
            if (rkeep && j <= climit)
                rowp[(j + 1) * TPB] = (unsigned char)m;           // d[i+1][j+1]
            prev[j] = left;
            left = m;
        }
        res = left;                        // d[i+1][wlen+1]
    }

    if (slot < NW) out[q * NW + orig] = (float)res;
}

// -------------------------------------------------------------------------
extern "C" void kernel_launch(void* const* d_in, const int* in_sizes, int n_in,
                              void* d_out, int out_size) {
    const int* x     = (const int*)d_in[0];   // (2,16,15) int32
    const int* words = (const int*)d_in[1];   // (10000,14) int32
    const int* wl    = (const int*)d_in[2];   // (10000,) int32
    float* out = (float*)d_out;               // (2,16,10000) float32

    hist_kernel<<<1, 256>>>(wl);
    scatter_pack_kernel<<<(NW + 255) / 256, 256>>>(words, wl);
    dim3 grid((NW + TPB - 1) / TPB, QCOUNT);
    dl_kernel<<<grid, TPB>>>(x, out);
}

// round 3
// speedup vs baseline: 1.3821x; 1.0082x over previous
#include <cuda_runtime.h>

#define NW      10000
#define MAXLEN  14
#define QCOUNT  32     // BSZ*SEQ
#define TPB     64
#define SORT_B  256    // threads per sort block
#define NSB     ((NW + SORT_B - 1) / SORT_B)   // 40 sort blocks

// Scratch (no allocation allowed)
__device__ int   g_wlen_s[NW];
__device__ int   g_orig_s[NW];
__device__ uint4 g_packed[NW];

// -------------------------------------------------------------------------
// Fused counting-sort: every block scans the whole wl array (L2-resident,
// int4 vectorized) to build the GLOBAL length histogram and a
// "predecessors before this block" histogram. Then:
//   pos = excl_prefix[len] + before_block[len] + rank_in_block
// No inter-block dependency, no global atomics, one launch.
// Within-block rank is atomic-nondeterministic; dl scatters by orig index,
// so final output is deterministic.
// -------------------------------------------------------------------------
__global__ void __launch_bounds__(SORT_B)
fused_sort_kernel(const int* __restrict__ words, const int* __restrict__ wl) {
    __shared__ int h_all[MAXLEN + 2];
    __shared__ int h_bef[MAXLEN + 2];
    __shared__ int h_rank[MAXLEN + 2];
    __shared__ int base[MAXLEN + 2];

    const int t = threadIdx.x;
    const int blockStart = blockIdx.x * SORT_B;

    if (t <= MAXLEN + 1) { h_all[t] = 0; h_bef[t] = 0; h_rank[t] = 0; }
    __syncthreads();

    // Full scan of wl (10000 ints = 2500 int4), counting all + before-block
    const uint4* wl4 = (const uint4*)wl;
    for (int v = t; v < NW / 4; v += SORT_B) {
        uint4 w4 = wl4[v];
        int idx = v * 4;
        atomicAdd(&h_all[w4.x], 1); if (idx + 0 < blockStart) atomicAdd(&h_bef[w4.x], 1);
        atomicAdd(&h_all[w4.y], 1); if (idx + 1 < blockStart) atomicAdd(&h_bef[w4.y], 1);
        atomicAdd(&h_all[w4.z], 1); if (idx + 2 < blockStart) atomicAdd(&h_bef[w4.z], 1);
        atomicAdd(&h_all[w4.w], 1); if (idx + 3 < blockStart) atomicAdd(&h_bef[w4.w], 1);
    }
    __syncthreads();

    if (t == 0) {
        int acc = 0;
        for (int l = 1; l <= MAXLEN; ++l) { base[l] = acc; acc += h_all[l]; }
    }
    __syncthreads();

    const int w = blockStart + t;
    if (w < NW) {
        int len  = wl[w];
        int rank = atomicAdd(&h_rank[len], 1);
        int pos  = base[len] + h_bef[len] + rank;
        g_wlen_s[pos] = len;
        g_orig_s[pos] = w;
        unsigned int p[4] = {0u, 0u, 0u, 0u};
        #pragma unroll
        for (int c = 0; c < MAXLEN; ++c) {
            unsigned int ch = (unsigned int)words[w * MAXLEN + c] & 0xFFu;
            p[c >> 2] |= ch << ((c & 3) * 8);
        }
        g_packed[pos] = make_uint4(p[0], p[1], p[2], p[3]);
    }
}

// -------------------------------------------------------------------------
// Main kernel. One thread per (query, sorted word). Previous DP row in
// registers; a 14x16 per-thread byte matrix in smem serves only the
// transposition gather d[k][l] (k<=swl-1<=13, l<=wlen-1<=13).
// -------------------------------------------------------------------------
__global__ void __launch_bounds__(TPB)
dl_kernel(const int* __restrict__ x, float* __restrict__ out) {
    __shared__ unsigned char d_s[14 * 16 * TPB];   // 224 B per thread
    __shared__ int s_x[MAXLEN + 1];

    const int tid  = threadIdx.x;
    const int q    = blockIdx.y;
    const int slot = blockIdx.x * TPB + tid;

    if (tid < MAXLEN + 1) s_x[tid] = x[q * (MAXLEN + 1) + tid];
    __syncthreads();

    // swl = first-argmax over the 15 chars (jnp.argmax semantics)
    int swl = 0, best = s_x[0];
    #pragma unroll
    for (int t = 1; t <= MAXLEN; ++t) {
        int v = s_x[t];
        if (v > best) { best = v; swl = t; }
    }

    int wlen = 0, orig = 0;
    unsigned int pw0 = 0, pw1 = 0, pw2 = 0, pw3 = 0;
    if (slot < NW) {
        wlen = g_wlen_s[slot];
        orig = g_orig_s[slot];
        uint4 p = g_packed[slot];
        pw0 = p.x; pw1 = p.y; pw2 = p.z; pw3 = p.w;
    }

    int wc[MAXLEN];
    #pragma unroll
    for (int c = 0; c < MAXLEN; ++c) {
        unsigned int r = (c < 4) ? pw0 : (c < 8) ? pw1 : (c < 12) ? pw2 : pw3;
        wc[c] = (int)((r >> ((c & 3) * 8)) & 0xFFu);
    }
    int kreg[MAXLEN];
    #pragma unroll
    for (int c = 0; c < MAXLEN; ++c) kreg[c] = 0;

    const int maxd = swl + wlen;
    unsigned char* bp = d_s + tid;

    // Init gather-reachable boundary cells (rows 0..swl-1, cols 0..wlen-1):
    //   d[0][l] = maxd ; d[1][0] = maxd ; d[1][l>=1] = l-1
    //   d[k][0] = maxd, d[k][1] = k-1   for k = 2..swl-1
    for (int l = 0; l < wlen; ++l) {
        bp[(0 * 16 + l) * TPB] = (unsigned char)maxd;
        bp[(1 * 16 + l) * TPB] = (unsigned char)(l == 0 ? maxd : l - 1);
    }
    for (int k = 2; k < swl; ++k) {
        bp[(k * 16 + 0) * TPB] = (unsigned char)maxd;
        bp[(k * 16 + 1) * TPB] = (unsigned char)(k - 1);
    }

    // prev[j] = d[i][j]; row 1: d[1][j] = j-1
    int prev[16];
    #pragma unroll
    for (int j = 1; j <= 15; ++j) prev[j] = j - 1;

    int res = wlen;                        // swl == 0: d[1][wlen+1] = wlen
    const int rlimit = swl - 2;            // last row whose store matters
    const int climit = wlen - 2;           // last col whose store matters
    for (int i = 1; i <= swl; ++i) {       // uniform per block
        const int xc  = s_x[i - 1];
        const int im1 = i - 1;
        int db   = 0;
        int left = i;                      // d[i+1][1] = i
        unsigned char* rowp = bp + ((i + 1) * 16) * TPB;
        const bool rkeep = (i <= rlimit);
        #pragma unroll
        for (int j = 1; j <= 15; ++j) {
            if (j > wlen || j == 15) { prev[j] = left; break; }   // d[i+1][j]
            const bool p  = (xc == wc[j - 1]);
            const int up   = prev[j + 1];
            const int diag = prev[j];
            const int k = kreg[j - 1];
            const int l = db;
            const int dtr   = (int)bp[(k * 16 + l) * TPB];        // LDS.U8
            const int trans = dtr + (im1 + j - k - l);
            int m = min(up, left) + 1;
            m = min(m, diag + (p ? 0 : 1));
            m = min(m, trans);
            if (p) { db = j; kreg[j - 1] = i; }
            if (rkeep && j <= climit)
                rowp[(j + 1) * TPB] = (unsigned char)m;           // d[i+1][j+1]
            prev[j] = left;
            left = m;
        }
        res = left;                        // d[i+1][wlen+1]
    }

    if (slot < NW) out[q * NW + orig] = (float)res;
}

// -------------------------------------------------------------------------
extern "C" void kernel_launch(void* const* d_in, const int* in_sizes, int n_in,
                              void* d_out, int out_size) {
    const int* x     = (const int*)d_in[0];   // (2,16,15) int32
    const int* words = (const int*)d_in[1];   // (10000,14) int32
    const int* wl    = (const int*)d_in[2];   // (10000,) int32
    float* out = (float*)d_out;               // (2,16,10000) float32

    fused_sort_kernel<<<NSB, SORT_B>>>(words, wl);
    dim3 grid((NW + TPB - 1) / TPB, QCOUNT);
    dl_kernel<<<grid, TPB>>>(x, out);
}